// round 17
// baseline (speedup 1.0000x reference)
#include <cuda_runtime.h>
#include <cuda_fp16.h>
#include <math.h>

// ---------------- fixed CT geometry ----------------
#define IMG   512
#define NDET  768
#define NV    360

#define PIXd  0.7433
#define DSOd  595.0
#define DSDd  1085.6              // 595.0 + 490.6
#define DETd  1.2858
#define DGd   (DETd / DSDd)       // equiangular pitch (rad/bin)
#define INVDGd (DSDd / DETd)
#define SCALEd (DGd * 2.0 * M_PI / 360.0)   // fold q*=DGAMMA and *=2pi/NV

// padded q row: [16 zero | 768 data | 16 zero]; i0 in [-13,779] stays in-row
#define QPAD    16
#define QSTRIDE 800

// Interleaved pack: for view-group g (views g, g+90, g+180, g+270) and bin d,
// one 32-byte struct = 4 x (a=(q0,q1), b=(dq0,dq1)) fp16 pairs.
// bp reads it with two LDG.128 at ONE address (same i0 for all 4 views,
// guaranteed by the rotation symmetry).
struct __align__(16) QQ { __half2 a0, b0, a1, b1, a2, b2, a3, b3; };

// ---------------- device scratch (no allocations allowed) ----------------
__device__ float2 cs_tab[NV];               // (cos beta, sin beta)
__device__ float2 q_part[4][NV * NDET];     // split-K quarter partials
__device__ QQ     q_pack[(NV / 4) * QSTRIDE]; // interleaved, zero-padded
__device__ float  part_img[3][2 * IMG * IMG]; // rot-90/180/270 contributions

// ---------------- conv: block = (view pair, K quarter) ---------------------
// 2 views share each gs load: 4 LDS wavefronts serve 8 FMAs per iteration.
__global__ void __launch_bounds__(384) conv_kernel(const float* __restrict__ proj) {
    __shared__ float2 p2[2][192];            // [view][local tap], (batch0,batch1)
    __shared__ float  gsl[959];              // this quarter's ramp taps

    const int pair = blockIdx.x >> 2;
    const int Q    = blockIdx.x & 3;
    const int v0   = 2 * pair;
    const int tid  = threadIdx.x;

    if (Q == 0 && tid < 2) {                 // per-view angles (double-accurate)
        double sb, cb;
        sincospi((double)(v0 + tid) / 180.0, &sb, &cb);
        cs_tab[v0 + tid] = make_float2((float)cb, (float)sb);
    }
    for (int i = tid; i < 959; i += 384) {   // ramp taps (fp32: 2e-7 rel)
        int n = i - 191 - 192 * Q;
        float g;
        if (n == 0) {
            g = (float)(SCALEd / (8.0 * DGd * DGd));
        } else if (n & 1) {
            float s = sinf((float)n * (float)DGd) * (float)M_PI;
            g = (float)(-0.5 * SCALEd) / (s * s);
        } else {
            g = 0.0f;
        }
        gsl[i] = g;
    }
    {   // cosine-weighted projections: 2 views x 192 bins, one per thread
        int view = tid / 192;                // 0 or 1
        int kk   = tid % 192;
        int bin  = 192 * Q + kk;
        int v    = v0 + view;
        float gam = ((float)bin - 383.5f) * (float)DGd;
        float cw  = 595.0f * cosf(gam);
        p2[view][kk] = make_float2(proj[(0 * NV + v) * NDET + bin] * cw,
                                   proj[(1 * NV + v) * NDET + bin] * cw);
    }
    __syncthreads();

    const int t  = tid;                      // outputs t and t+384
    const int t2 = tid + 384;
    const float g0 = (float)(SCALEd / (8.0 * DGd * DGd));

    float a0 = 0.f, a1 = 0.f, a2 = 0.f, a3 = 0.f;   // view v0: (t b0,b1), (t2 b0,b1)
    float b0 = 0.f, b1 = 0.f, b2 = 0.f, b3 = 0.f;   // view v0+1

    if (t >= 192 * Q && t < 192 * Q + 192) {        // center tap (n=0)
        float2 pa = p2[0][t - 192 * Q], pb = p2[1][t - 192 * Q];
        a0 = pa.x * g0; a1 = pa.y * g0;
        b0 = pb.x * g0; b1 = pb.y * g0;
    }
    if (t2 >= 192 * Q && t2 < 192 * Q + 192) {
        float2 pa = p2[0][t2 - 192 * Q], pb = p2[1][t2 - 192 * Q];
        a2 = pa.x * g0; a3 = pa.y * g0;
        b2 = pb.x * g0; b3 = pb.y * g0;
    }

    const int k0 = (t + 1) & 1;              // local parity making (t-k) odd
#pragma unroll 8
    for (int kk = k0; kk < 192; kk += 2) {
        float2 pa = p2[0][kk];               // broadcast LDS.64
        float2 pb = p2[1][kk];               // broadcast LDS.64
        float gva = gsl[t  - kk + 191];      // stride-1
        float gvb = gsl[t2 - kk + 191];      // stride-1 (offset +384)
        a0 = fmaf(pa.x, gva, a0);
        a1 = fmaf(pa.y, gva, a1);
        a2 = fmaf(pa.x, gvb, a2);
        a3 = fmaf(pa.y, gvb, a3);
        b0 = fmaf(pb.x, gva, b0);
        b1 = fmaf(pb.y, gva, b1);
        b2 = fmaf(pb.x, gvb, b2);
        b3 = fmaf(pb.y, gvb, b3);
    }
    q_part[Q][ v0      * NDET + t ] = make_float2(a0, a1);
    q_part[Q][ v0      * NDET + t2] = make_float2(a2, a3);
    q_part[Q][(v0 + 1) * NDET + t ] = make_float2(b0, b1);
    q_part[Q][(v0 + 1) * NDET + t2] = make_float2(b2, b3);
}

// ---------------- pack: sum quarters + pre-diff + interleave 4 views -------
// Block = view group g; gathers views g, g+90, g+180, g+270.
__global__ void __launch_bounds__(NDET) pack_kernel() {
    __shared__ float2 qs[4][NDET];
    const int g = blockIdx.x;                // 0..89
    const int t = threadIdx.x;

#pragma unroll
    for (int r = 0; r < 4; ++r) {
        int v = g + r * (NV / 4);
        float2 p0 = q_part[0][v * NDET + t];
        float2 p1 = q_part[1][v * NDET + t];
        float2 p2 = q_part[2][v * NDET + t];
        float2 p3 = q_part[3][v * NDET + t];
        qs[r][t] = make_float2((p0.x + p1.x) + (p2.x + p3.x),
                               (p0.y + p1.y) + (p2.y + p3.y));
    }
    if (t < QPAD) {
        QQ z;
        z.a0 = z.b0 = z.a1 = z.b1 = z.a2 = z.b2 = z.a3 = z.b3 =
            __floats2half2_rn(0.f, 0.f);
        q_pack[g * QSTRIDE + t]               = z;
        q_pack[g * QSTRIDE + QPAD + NDET + t] = z;
    }
    __syncthreads();

    const int dn = min(t + 1, NDET - 1);
    QQ o;
    {
        float2 qa = qs[0][t], qb = qs[0][dn];
        o.a0 = __floats2half2_rn(qa.x, qa.y);
        o.b0 = __floats2half2_rn(qb.x - qa.x, qb.y - qa.y);
    }
    {
        float2 qa = qs[1][t], qb = qs[1][dn];
        o.a1 = __floats2half2_rn(qa.x, qa.y);
        o.b1 = __floats2half2_rn(qb.x - qa.x, qb.y - qa.y);
    }
    {
        float2 qa = qs[2][t], qb = qs[2][dn];
        o.a2 = __floats2half2_rn(qa.x, qa.y);
        o.b2 = __floats2half2_rn(qb.x - qa.x, qb.y - qa.y);
    }
    {
        float2 qa = qs[3][t], qb = qs[3][dn];
        o.a3 = __floats2half2_rn(qa.x, qa.y);
        o.b3 = __floats2half2_rn(qb.x - qa.x, qb.y - qa.y);
    }
    q_pack[g * QSTRIDE + QPAD + t] = o;
}

// ---------------- backprojection with 4-fold rotation symmetry -------------
// One geometry per (pixel, view-group); 2 LDG.128 at one address feed all
// four view updates (same i0 by symmetry). HFMA2 interpolation.
__global__ void __launch_bounds__(128, 12) bp_kernel(float* __restrict__ out) {
    __shared__ float2 cs_s[NV / 4];
    const int tid = threadIdx.y * 16 + threadIdx.x;
    if (tid < NV / 4) cs_s[tid] = cs_tab[tid];
    __syncthreads();

    const int j = (blockIdx.x << 4) + threadIdx.x;
    const int i = (blockIdx.y << 3) + threadIdx.y;

    const float x = ((float)j - 255.5f) * (float)PIXd;
    const float y = ((float)i - 255.5f) * (float)PIXd;
    const float DSOf = 595.0f;

    // asin Taylor coefficients * (1/DGAMMA), degree 13
    const float A0 = (float)(INVDGd);
    const float A1 = (float)(INVDGd / 6.0);
    const float A2 = (float)(INVDGd * 0.075);
    const float A3 = (float)(INVDGd * 0.044642857);
    const float A4 = (float)(INVDGd * 0.030381944);
    const float A5 = (float)(INVDGd * 0.022372159);
    const float A6 = (float)(INVDGd * 0.017352764);

    float aS0 = 0.f, aS1 = 0.f;              // self pixel,     views 0..89
    float a90_0 = 0.f, a90_1 = 0.f;          // rot +90 pixel,  views 90..179
    float a180_0 = 0.f, a180_1 = 0.f;        // rot 180 pixel,  views 180..269
    float a270_0 = 0.f, a270_1 = 0.f;        // rot 270 pixel,  views 270..359

    const QQ* __restrict__ qp = q_pack + QPAD;

#pragma unroll 3
    for (int v = 0; v < NV / 4; ++v) {
        float2 cs = cs_s[v];
        float u  = fmaf(cs.x, x,  cs.y * y);
        float cr = fmaf(cs.y, x, -cs.x * y);
        float dt = DSOf - u;
        float L2 = fmaf(dt, dt, cr * cr);
        float rsq;
        asm("rsqrt.approx.f32 %0, %1;" : "=f"(rsq) : "f"(L2));
        float s  = cr * rsq;                 // sin(theta), dt > 0 always
        float s2 = s * s;
        float p  = fmaf(A6, s2, A5);
        p = fmaf(p, s2, A4);
        p = fmaf(p, s2, A3);
        p = fmaf(p, s2, A2);
        p = fmaf(p, s2, A1);
        p = fmaf(p, s2, A0);
        float tv = s * p;                    // g - 383.5 (detector offset)
        float g  = tv + 383.5f;

        float T  = (g - 0.5f) + 12582912.0f; // round(g-0.5) == floor(g)
        int   i0 = __float_as_int(T) - 0x4B400000;
        float fg = T - 12582912.0f;
        float w_ = g - fg;
        float m  = rsq * rsq;                // 1/L2
        float wl = (fabsf(tv) <= 383.5f) ? m : 0.0f;   // g in [0,767]
        __half2 w2 = __float2half2_rn(w_);

        const uint4* qv = (const uint4*)(qp + v * QSTRIDE + i0);
        uint4 lo = qv[0];                    // views v, v+90
        uint4 hi = qv[1];                    // views v+180, v+270
        __half2 qa_a = *(__half2*)&lo.x, qa_b = *(__half2*)&lo.y;
        __half2 qb_a = *(__half2*)&lo.z, qb_b = *(__half2*)&lo.w;
        __half2 qc_a = *(__half2*)&hi.x, qc_b = *(__half2*)&hi.y;
        __half2 qd_a = *(__half2*)&hi.z, qd_b = *(__half2*)&hi.w;
        float2 fa = __half22float2(__hfma2(w2, qa_b, qa_a));
        float2 fb = __half22float2(__hfma2(w2, qb_b, qb_a));
        float2 fc = __half22float2(__hfma2(w2, qc_b, qc_a));
        float2 fd = __half22float2(__hfma2(w2, qd_b, qd_a));
        aS0    = fmaf(fa.x, wl, aS0);
        aS1    = fmaf(fa.y, wl, aS1);
        a90_0  = fmaf(fb.x, wl, a90_0);
        a90_1  = fmaf(fb.y, wl, a90_1);
        a180_0 = fmaf(fc.x, wl, a180_0);
        a180_1 = fmaf(fc.y, wl, a180_1);
        a270_0 = fmaf(fd.x, wl, a270_0);
        a270_1 = fmaf(fd.y, wl, a270_1);
    }

    out[i * IMG + j]             = aS0;
    out[IMG * IMG + i * IMG + j] = aS1;
    // rot +90: pixel (i', j') = (j, 511-i)
    part_img[0][j * IMG + (IMG - 1 - i)]             = a90_0;
    part_img[0][IMG * IMG + j * IMG + (IMG - 1 - i)] = a90_1;
    // rot 180: (511-i, 511-j)
    part_img[1][(IMG - 1 - i) * IMG + (IMG - 1 - j)]             = a180_0;
    part_img[1][IMG * IMG + (IMG - 1 - i) * IMG + (IMG - 1 - j)] = a180_1;
    // rot 270: (511-j, i)
    part_img[2][(IMG - 1 - j) * IMG + i]             = a270_0;
    part_img[2][IMG * IMG + (IMG - 1 - j) * IMG + i] = a270_1;
}

// ---------------- combine: out += s90 + s180 + s270 ------------------------
__global__ void __launch_bounds__(256) combine_kernel(float* __restrict__ out) {
    int t = blockIdx.x * 256 + threadIdx.x;          // float4 index
    float4* o = (float4*)out;
    const float4* p0 = (const float4*)part_img[0];
    const float4* p1 = (const float4*)part_img[1];
    const float4* p2 = (const float4*)part_img[2];
    float4 a = o[t], b = p0[t], c = p1[t], d = p2[t];
    o[t] = make_float4(a.x + b.x + c.x + d.x,
                       a.y + b.y + c.y + d.y,
                       a.z + b.z + c.z + d.z,
                       a.w + b.w + c.w + d.w);
}

// ---------------- entry point ----------------
extern "C" void kernel_launch(void* const* d_in, const int* in_sizes, int n_in,
                              void* d_out, int out_size) {
    (void)in_sizes; (void)n_in; (void)out_size;
    const float* proj = (const float*)d_in[0];   // [2, 360, 768] f32
    float* out = (float*)d_out;                  // [2, 512, 512] f32

    conv_kernel<<<4 * (NV / 2), 384>>>(proj);
    pack_kernel<<<NV / 4, NDET>>>();
    bp_kernel<<<dim3(IMG / 16, IMG / 8), dim3(16, 8)>>>(out);
    combine_kernel<<<(2 * IMG * IMG / 4) / 256, 256>>>(out);
}